// round 6
// baseline (speedup 1.0000x reference)
#include <cuda_runtime.h>
#include <cstdint>
#include <cstddef>

#define NMAX 100000
#define HIDD 96

// ---------------- scratch (no allocations allowed) ----------------
__device__ __align__(16) float g_deg[NMAX];
__device__ __align__(16) float g_dinv[NMAX];
__device__ __align__(16) float g_hA[(size_t)NMAX * HIDD];   // GEMM output (pre-agg)
__device__ __align__(16) float g_hB[(size_t)NMAX * HIDD];   // post-BN/ReLU features
__device__ __align__(16) float g_agg[(size_t)NMAX * HIDD];  // aggregation accumulator
__device__ __align__(16) float g_stats[2 * HIDD];           // [sum | sumsq]

// ---------------- degree / dinv / zeroing ----------------
__global__ void k_deg_init(int N) {
    int i = blockIdx.x * blockDim.x + threadIdx.x;
    if (i < N) g_deg[i] = 1.0f;  // self loop
}
__global__ void k_deg_count(const int* __restrict__ dst, int E) {
    int e = blockIdx.x * blockDim.x + threadIdx.x;
    if (e < E) atomicAdd(&g_deg[dst[e]], 1.0f);
}
__global__ void k_dinv(int N) {
    int i = blockIdx.x * blockDim.x + threadIdx.x;
    if (i < N) g_dinv[i] = rsqrtf(g_deg[i]);
}
__global__ void k_zero_agg(int total4) {
    int i = blockIdx.x * blockDim.x + threadIdx.x;
    if (i < total4) ((float4*)g_agg)[i] = make_float4(0.f, 0.f, 0.f, 0.f);
}
__global__ void k_zero_stats() {
    int i = threadIdx.x;
    if (i < 2 * HIDD) g_stats[i] = 0.f;
}

// ---------------- GEMM: g_hA[N,OUT] = X[N,K] @ W[K,OUT] ----------------
// USE_HB=0: X comes from the pointer argument (harness input).
// USE_HB=1: X is the internal g_hB buffer (avoids passing __device__ symbol
//           addresses from host code, which is UB).
__device__ __forceinline__ float f4c(const float4& v, int kk) {
    switch (kk) { case 0: return v.x; case 1: return v.y; case 2: return v.z; default: return v.w; }
}

template <int K, int OUT, int RY, int USE_HB>
__global__ __launch_bounds__((OUT / 4) * RY)
void gemm_kernel(const float* __restrict__ Xarg, const float* __restrict__ W, int N) {
    constexpr int C4 = OUT / 4;
    __shared__ float4 Ws[K * C4];
    const int tid = threadIdx.y * C4 + threadIdx.x;
    const float4* W4 = (const float4*)W;
    for (int i = tid; i < K * C4; i += C4 * RY) Ws[i] = W4[i];
    __syncthreads();

    const float* X = USE_HB ? (const float*)g_hB : Xarg;

    const int c = threadIdx.x;
    const int r0 = (blockIdx.x * RY + threadIdx.y) * 4;
    if (r0 >= N) return;
    const bool full = (r0 + 3 < N);

    const float4* X4 = (const float4*)X;
    const int ldx = K / 4;

    float4 acc[4];
#pragma unroll
    for (int r = 0; r < 4; r++) acc[r] = make_float4(0.f, 0.f, 0.f, 0.f);

#pragma unroll 2
    for (int k4 = 0; k4 < K / 4; k4++) {
        float4 xr[4];
#pragma unroll
        for (int r = 0; r < 4; r++) {
            int row = r0 + r;
            xr[r] = (full || row < N) ? X4[(size_t)row * ldx + k4]
                                      : make_float4(0.f, 0.f, 0.f, 0.f);
        }
#pragma unroll
        for (int kk = 0; kk < 4; kk++) {
            float4 w = Ws[(k4 * 4 + kk) * C4 + c];
#pragma unroll
            for (int r = 0; r < 4; r++) {
                float xv = f4c(xr[r], kk);
                acc[r].x += xv * w.x; acc[r].y += xv * w.y;
                acc[r].z += xv * w.z; acc[r].w += xv * w.w;
            }
        }
    }

    float4* Y4 = (float4*)g_hA;
#pragma unroll
    for (int r = 0; r < 4; r++) {
        int row = r0 + r;
        if (full || row < N) Y4[(size_t)row * C4 + c] = acc[r];
    }
}

// ---------------- edge scatter: g_agg[d] += dinv[s]*dinv[d]*g_hA[s] ----------------
// 8 lanes per edge; each lane loads float4s of h[s] and issues scalar
// atomicAdd (REDG.ADD.F32, no-return) into agg[d].
template <int F4>
__global__ void scatter_kernel(const int* __restrict__ src,
                               const int* __restrict__ dst, int E) {
    constexpr int LPE = 8;
    constexpr int F4PL = F4 / LPE;
    int t = blockIdx.x * blockDim.x + threadIdx.x;
    int e = t / LPE;
    int sub = t % LPE;
    if (e >= E) return;
    int s = src[e];
    int d = dst[e];
    float nrm = g_dinv[s] * g_dinv[d];
    const float4* hs = (const float4*)g_hA + (size_t)s * F4;
    float* ad = g_agg + (size_t)d * (F4 * 4);
#pragma unroll
    for (int j = 0; j < F4PL; j++) {
        int f = sub + j * LPE;
        float4 v = hs[f];
        atomicAdd(ad + f * 4 + 0, v.x * nrm);
        atomicAdd(ad + f * 4 + 1, v.y * nrm);
        atomicAdd(ad + f * 4 + 2, v.z * nrm);
        atomicAdd(ad + f * 4 + 3, v.w * nrm);
    }
}

// ---------------- finish: v = agg + dinv^2*h + b; accumulate BN stats ----------------
template <int F>
__global__ void finish_kernel(const float* __restrict__ bias, int N) {
    const int f = threadIdx.x;   // blockDim = (F, 4)
    const float b = bias[f];
    float ls = 0.f, lss = 0.f;
    for (int i = blockIdx.x * 4 + threadIdx.y; i < N; i += gridDim.x * 4) {
        float di = g_dinv[i];
        size_t idx = (size_t)i * F + f;
        float v = g_agg[idx] + di * di * g_hA[idx] + b;
        g_agg[idx] = v;
        ls += v; lss += v * v;
    }
    __shared__ float ssum[4][F];
    __shared__ float ssq[4][F];
    ssum[threadIdx.y][f] = ls;
    ssq[threadIdx.y][f] = lss;
    __syncthreads();
    if (threadIdx.y == 0) {
        float a = ssum[0][f] + ssum[1][f] + ssum[2][f] + ssum[3][f];
        float q = ssq[0][f] + ssq[1][f] + ssq[2][f] + ssq[3][f];
        atomicAdd(&g_stats[f], a);
        atomicAdd(&g_stats[F + f], q);
    }
}

// ---------------- BN apply + ReLU: g_hB = relu(bn(g_agg)) ----------------
template <int F>
__global__ void bn_relu_kernel(const float* __restrict__ gamma,
                               const float* __restrict__ beta, int N) {
    int idx = blockIdx.x * blockDim.x + threadIdx.x;
    int total = N * F;
    if (idx >= total) return;
    int f = idx - (idx / F) * F;
    float invN = 1.0f / (float)N;
    float mu = g_stats[f] * invN;
    float var = g_stats[F + f] * invN - mu * mu;
    float y = gamma[f] * (g_agg[idx] - mu) * rsqrtf(var + 1e-5f) + beta[f];
    g_hB[idx] = fmaxf(y, 0.f);
}

// ---------------- layer-3 finish + log_softmax (warp per node, 32 classes) ----------------
__global__ void finish_softmax_kernel(const float* __restrict__ b3,
                                      float* __restrict__ out, int N) {
    int warps_per_block = blockDim.x / 32;
    int i = blockIdx.x * warps_per_block + (threadIdx.x >> 5);
    int lane = threadIdx.x & 31;
    if (i >= N) return;
    float di = g_dinv[i];
    size_t idx = (size_t)i * 32 + lane;
    float v = g_agg[idx] + di * di * g_hA[idx] + b3[lane];
    float m = v;
#pragma unroll
    for (int o = 16; o > 0; o >>= 1) m = fmaxf(m, __shfl_xor_sync(0xFFFFFFFFu, m, o));
    float s = expf(v - m);
#pragma unroll
    for (int o = 16; o > 0; o >>= 1) s += __shfl_xor_sync(0xFFFFFFFFu, s, o);
    out[idx] = v - m - logf(s);
}

// ---------------- host ----------------
extern "C" void kernel_launch(void* const* d_in, const int* in_sizes, int n_in,
                              void* d_out, int out_size) {
    const float* x  = (const float*)d_in[0];
    // edge_index: JAX default x64-disabled -> int32 despite jnp.int64 request.
    const int* ei   = (const int*)d_in[1];
    const float* W1 = (const float*)d_in[2];
    const float* b1 = (const float*)d_in[3];
    const float* W2 = (const float*)d_in[4];
    const float* b2 = (const float*)d_in[5];
    const float* W3 = (const float*)d_in[6];
    const float* b3 = (const float*)d_in[7];
    const float* g1 = (const float*)d_in[8];
    const float* be1 = (const float*)d_in[9];
    const float* g2 = (const float*)d_in[10];
    const float* be2 = (const float*)d_in[11];
    float* out = (float*)d_out;

    int N = in_sizes[0] / 128;
    int E = in_sizes[1] / 2;
    const int* src = ei;
    const int* dst = ei + E;

    // --- degrees (recomputed every call: deterministic, cheap) ---
    k_deg_init<<<(N + 255) / 256, 256>>>(N);
    k_deg_count<<<(E + 255) / 256, 256>>>(dst, E);
    k_dinv<<<(N + 255) / 256, 256>>>(N);

    // --- layer 1: 128 -> 96 ---
    gemm_kernel<128, 96, 8, 0><<<(N + 31) / 32, dim3(24, 8)>>>(x, W1, N);
    k_zero_agg<<<(N * 24 + 255) / 256, 256>>>(N * 24);
    scatter_kernel<24><<<(E * 8 + 255) / 256, 256>>>(src, dst, E);
    k_zero_stats<<<1, 2 * HIDD>>>();
    finish_kernel<96><<<256, dim3(96, 4)>>>(b1, N);
    bn_relu_kernel<96><<<(N * 96 + 255) / 256, 256>>>(g1, be1, N);

    // --- layer 2: 96 -> 96 ---
    gemm_kernel<96, 96, 8, 1><<<(N + 31) / 32, dim3(24, 8)>>>(nullptr, W2, N);
    k_zero_agg<<<(N * 24 + 255) / 256, 256>>>(N * 24);
    scatter_kernel<24><<<(E * 8 + 255) / 256, 256>>>(src, dst, E);
    k_zero_stats<<<1, 2 * HIDD>>>();
    finish_kernel<96><<<256, dim3(96, 4)>>>(b2, N);
    bn_relu_kernel<96><<<(N * 96 + 255) / 256, 256>>>(g2, be2, N);

    // --- layer 3: 96 -> 32, then log_softmax ---
    gemm_kernel<96, 32, 16, 1><<<(N + 63) / 64, dim3(8, 16)>>>(nullptr, W3, N);
    k_zero_agg<<<(N * 8 + 255) / 256, 256>>>(N * 8);
    scatter_kernel<8><<<(E * 8 + 255) / 256, 256>>>(src, dst, E);
    finish_softmax_kernel<<<(N + 7) / 8, 256>>>(b3, out, N);
}

// round 8
// speedup vs baseline: 1.4960x; 1.4960x over previous
#include <cuda_runtime.h>
#include <cstdint>
#include <cstddef>

#define NMAX 100000
#define EMAX 800000
#define HIDD 96
#define SCAN_BLK 1024
#define SCAN_NB ((NMAX + SCAN_BLK - 1) / SCAN_BLK)   // 98

// ---------------- scratch (no allocations allowed) ----------------
__device__ __align__(16) float g_dinv[NMAX];
__device__ __align__(16) float g_hA[(size_t)NMAX * HIDD];   // GEMM output (pre-agg)
__device__ __align__(16) float g_hB[(size_t)NMAX * HIDD];   // post-BN/ReLU features
__device__ __align__(16) float g_agg[(size_t)NMAX * HIDD];  // gather output (pre-BN)
__device__ __align__(16) float g_stats[2 * HIDD];           // [sum | sumsq]
__device__ int g_cnt[NMAX];
__device__ int g_off[NMAX + 1];
__device__ int g_cur[NMAX];
__device__ int g_srcs[EMAX];
__device__ int g_bsum[128];

// ---------------- CSR build ----------------
__global__ void k_zero_cnt(int N) {
    int i = blockIdx.x * blockDim.x + threadIdx.x;
    if (i < N) { g_cnt[i] = 0; g_cur[i] = 0; }
}
__global__ void k_hist(const int* __restrict__ dst, int E) {
    int e = blockIdx.x * blockDim.x + threadIdx.x;
    if (e < E) atomicAdd(&g_cnt[dst[e]], 1);
}
__global__ void k_scan_block(int N) {   // grid = SCAN_NB, block = SCAN_BLK
    __shared__ int s[SCAN_BLK];
    int i = blockIdx.x * SCAN_BLK + threadIdx.x;
    int v = (i < N) ? g_cnt[i] : 0;
    s[threadIdx.x] = v;
    __syncthreads();
#pragma unroll
    for (int o = 1; o < SCAN_BLK; o <<= 1) {
        int t = (threadIdx.x >= o) ? s[threadIdx.x - o] : 0;
        __syncthreads();
        s[threadIdx.x] += t;
        __syncthreads();
    }
    if (i < N) g_off[i + 1] = s[threadIdx.x];
    if (threadIdx.x == SCAN_BLK - 1) g_bsum[blockIdx.x] = s[SCAN_BLK - 1];
}
__global__ void k_scan_bsum(int nb) {   // 1 block, 128 threads (nb <= 128)
    __shared__ int s[128];
    int v = (threadIdx.x < nb) ? g_bsum[threadIdx.x] : 0;
    s[threadIdx.x] = v;
    __syncthreads();
#pragma unroll
    for (int o = 1; o < 128; o <<= 1) {
        int t = (threadIdx.x >= o) ? s[threadIdx.x - o] : 0;
        __syncthreads();
        s[threadIdx.x] += t;
        __syncthreads();
    }
    if (threadIdx.x < nb) g_bsum[threadIdx.x] = s[threadIdx.x];
}
__global__ void k_scan_add(int N) {     // grid = SCAN_NB, block = SCAN_BLK
    int i = blockIdx.x * SCAN_BLK + threadIdx.x;
    if (blockIdx.x > 0 && i < N) g_off[i + 1] += g_bsum[blockIdx.x - 1];
    if (i == 0) g_off[0] = 0;
}
__global__ void k_dinv(int N) {
    int i = blockIdx.x * blockDim.x + threadIdx.x;
    if (i < N) g_dinv[i] = rsqrtf((float)(g_cnt[i] + 1));   // +1 self loop
}
__global__ void k_reorder(const int* __restrict__ src, const int* __restrict__ dst, int E) {
    int e = blockIdx.x * blockDim.x + threadIdx.x;
    if (e < E) {
        int d = dst[e];
        int pos = g_off[d] + atomicAdd(&g_cur[d], 1);
        g_srcs[pos] = src[e];
    }
}
__global__ void k_zero_stats() {
    int i = threadIdx.x;
    if (i < 2 * HIDD) g_stats[i] = 0.f;
}

// ---------------- GEMM: g_hA[N,OUT] = X[N,K] @ W[K,OUT] ----------------
// 8 rows x 8 cols per thread. W staged in SMEM. USE_HB=1 -> X = g_hB.
__device__ __forceinline__ float f4c(const float4& v, int kk) {
    switch (kk) { case 0: return v.x; case 1: return v.y; case 2: return v.z; default: return v.w; }
}

template <int K, int OUT, int RY, int USE_HB>
__global__ __launch_bounds__((OUT / 8) * RY)
void gemm_kernel(const float* __restrict__ Xarg, const float* __restrict__ W, int N) {
    constexpr int CG = OUT / 8;   // thread col-groups
    constexpr int C4 = OUT / 4;
    __shared__ float4 Ws[K * C4];
    const int tid = threadIdx.y * CG + threadIdx.x;
    const float4* W4 = (const float4*)W;
    for (int i = tid; i < K * C4; i += CG * RY) Ws[i] = W4[i];
    __syncthreads();

    const float* X = USE_HB ? (const float*)g_hB : Xarg;
    const int c = threadIdx.x;
    const int r0 = (blockIdx.x * RY + threadIdx.y) * 8;
    if (r0 >= N) return;
    const bool full = (r0 + 7 < N);

    const float4* X4 = (const float4*)X;
    constexpr int ldx = K / 4;

    float4 acc[8][2];
#pragma unroll
    for (int r = 0; r < 8; r++) {
        acc[r][0] = make_float4(0.f, 0.f, 0.f, 0.f);
        acc[r][1] = make_float4(0.f, 0.f, 0.f, 0.f);
    }

    for (int k4 = 0; k4 < K / 4; k4++) {
        float4 xr[8];
#pragma unroll
        for (int r = 0; r < 8; r++) {
            int row = r0 + r;
            xr[r] = (full || row < N) ? X4[(size_t)row * ldx + k4]
                                      : make_float4(0.f, 0.f, 0.f, 0.f);
        }
#pragma unroll
        for (int kk = 0; kk < 4; kk++) {
            float4 w0 = Ws[(k4 * 4 + kk) * C4 + 2 * c];
            float4 w1 = Ws[(k4 * 4 + kk) * C4 + 2 * c + 1];
#pragma unroll
            for (int r = 0; r < 8; r++) {
                float xv = f4c(xr[r], kk);
                acc[r][0].x += xv * w0.x; acc[r][0].y += xv * w0.y;
                acc[r][0].z += xv * w0.z; acc[r][0].w += xv * w0.w;
                acc[r][1].x += xv * w1.x; acc[r][1].y += xv * w1.y;
                acc[r][1].z += xv * w1.z; acc[r][1].w += xv * w1.w;
            }
        }
    }

    float4* Y4 = (float4*)g_hA;
#pragma unroll
    for (int r = 0; r < 8; r++) {
        int row = r0 + r;
        if (full || row < N) {
            Y4[(size_t)row * C4 + 2 * c]     = acc[r][0];
            Y4[(size_t)row * C4 + 2 * c + 1] = acc[r][1];
        }
    }
}

// ---------------- gather96: warp per node, CSR in-edges ----------------
// v[d] = dinv[d] * ( sum_{s in in(d)} dinv[s]*h[s] + dinv[d]*h[d] ) + b
// Fused BN-stat accumulation (smem reduce -> global atomics).
__global__ __launch_bounds__(256)
void gather96_kernel(const float* __restrict__ bias, int N) {
    __shared__ float sred[192];
    const int tid = threadIdx.x;
    for (int i = tid; i < 192; i += 256) sred[i] = 0.f;
    __syncthreads();

    const int lane = tid & 31;
    const int w = tid >> 5;
    const int c0 = lane, c1 = lane + 32, c2 = lane + 64;
    const float b0 = bias[c0], b1 = bias[c1], b2 = bias[c2];
    const int nwarps = gridDim.x * 8;

    float s0 = 0.f, s1 = 0.f, s2 = 0.f;       // BN sums
    float q0 = 0.f, q1 = 0.f, q2 = 0.f;       // BN sumsq

    for (int d = blockIdx.x * 8 + w; d < N; d += nwarps) {
        const int beg = g_off[d];
        const int end = g_off[d + 1];
        float a0 = 0.f, a1 = 0.f, a2 = 0.f;
        int j = beg;
        for (; j + 1 < end; j += 2) {
            int sa = g_srcs[j], sb = g_srcs[j + 1];
            float na = g_dinv[sa], nb = g_dinv[sb];
            const float* ha = g_hA + (size_t)sa * 96;
            const float* hb = g_hA + (size_t)sb * 96;
            float a0a = ha[c0], a1a = ha[c1], a2a = ha[c2];
            float a0b = hb[c0], a1b = hb[c1], a2b = hb[c2];
            a0 += na * a0a + nb * a0b;
            a1 += na * a1a + nb * a1b;
            a2 += na * a2a + nb * a2b;
        }
        if (j < end) {
            int sa = g_srcs[j];
            float na = g_dinv[sa];
            const float* ha = g_hA + (size_t)sa * 96;
            a0 += na * ha[c0]; a1 += na * ha[c1]; a2 += na * ha[c2];
        }
        const float dd = g_dinv[d];
        const float* hd = g_hA + (size_t)d * 96;
        a0 += dd * hd[c0]; a1 += dd * hd[c1]; a2 += dd * hd[c2];
        float v0 = dd * a0 + b0;
        float v1 = dd * a1 + b1;
        float v2 = dd * a2 + b2;
        float* od = g_agg + (size_t)d * 96;
        od[c0] = v0; od[c1] = v1; od[c2] = v2;
        s0 += v0; s1 += v1; s2 += v2;
        q0 += v0 * v0; q1 += v1 * v1; q2 += v2 * v2;
    }

    atomicAdd(&sred[c0], s0); atomicAdd(&sred[c1], s1); atomicAdd(&sred[c2], s2);
    atomicAdd(&sred[96 + c0], q0); atomicAdd(&sred[96 + c1], q1); atomicAdd(&sred[96 + c2], q2);
    __syncthreads();
    for (int i = tid; i < 192; i += 256) atomicAdd(&g_stats[i], sred[i]);
}

// ---------------- BN apply + ReLU: g_hB = relu(bn(g_agg)) ----------------
__global__ void bn_relu_kernel(const float* __restrict__ gamma,
                               const float* __restrict__ beta, int N) {
    int idx = blockIdx.x * blockDim.x + threadIdx.x;
    int total = N * HIDD;
    if (idx >= total) return;
    int f = idx - (idx / HIDD) * HIDD;
    float invN = 1.0f / (float)N;
    float mu = g_stats[f] * invN;
    float var = g_stats[HIDD + f] * invN - mu * mu;
    float y = gamma[f] * (g_agg[idx] - mu) * rsqrtf(var + 1e-5f) + beta[f];
    g_hB[idx] = fmaxf(y, 0.f);
}

// ---------------- layer-3: gather(32) + log_softmax, warp per node ----------------
__global__ __launch_bounds__(256)
void gather32_softmax_kernel(const float* __restrict__ b3, float* __restrict__ out, int N) {
    int d = blockIdx.x * 8 + (threadIdx.x >> 5);
    int lane = threadIdx.x & 31;
    if (d >= N) return;
    const int beg = g_off[d];
    const int end = g_off[d + 1];
    float a = 0.f;
    int j = beg;
    for (; j + 1 < end; j += 2) {
        int sa = g_srcs[j], sb = g_srcs[j + 1];
        float xa = g_hA[(size_t)sa * 32 + lane];
        float xb = g_hA[(size_t)sb * 32 + lane];
        a += g_dinv[sa] * xa + g_dinv[sb] * xb;
    }
    if (j < end) {
        int sa = g_srcs[j];
        a += g_dinv[sa] * g_hA[(size_t)sa * 32 + lane];
    }
    float dd = g_dinv[d];
    a += dd * g_hA[(size_t)d * 32 + lane];
    float v = dd * a + b3[lane];
    float m = v;
#pragma unroll
    for (int o = 16; o > 0; o >>= 1) m = fmaxf(m, __shfl_xor_sync(0xFFFFFFFFu, m, o));
    float s = expf(v - m);
#pragma unroll
    for (int o = 16; o > 0; o >>= 1) s += __shfl_xor_sync(0xFFFFFFFFu, s, o);
    out[(size_t)d * 32 + lane] = v - m - logf(s);
}

// ---------------- host ----------------
extern "C" void kernel_launch(void* const* d_in, const int* in_sizes, int n_in,
                              void* d_out, int out_size) {
    const float* x  = (const float*)d_in[0];
    const int* ei   = (const int*)d_in[1];   // int32 in practice (JAX x64 disabled)
    const float* W1 = (const float*)d_in[2];
    const float* b1 = (const float*)d_in[3];
    const float* W2 = (const float*)d_in[4];
    const float* b2 = (const float*)d_in[5];
    const float* W3 = (const float*)d_in[6];
    const float* b3 = (const float*)d_in[7];
    const float* g1 = (const float*)d_in[8];
    const float* be1 = (const float*)d_in[9];
    const float* g2 = (const float*)d_in[10];
    const float* be2 = (const float*)d_in[11];
    float* out = (float*)d_out;

    int N = in_sizes[0] / 128;
    int E = in_sizes[1] / 2;
    const int* src = ei;
    const int* dst = ei + E;

    // --- CSR build (once per call, reused by all 3 layers) ---
    int nb = (N + SCAN_BLK - 1) / SCAN_BLK;
    k_zero_cnt<<<(N + 255) / 256, 256>>>(N);
    k_hist<<<(E + 255) / 256, 256>>>(dst, E);
    k_scan_block<<<nb, SCAN_BLK>>>(N);
    k_scan_bsum<<<1, 128>>>(nb);
    k_scan_add<<<nb, SCAN_BLK>>>(N);
    k_dinv<<<(N + 255) / 256, 256>>>(N);
    k_reorder<<<(E + 255) / 256, 256>>>(src, dst, E);

    // --- layer 1: 128 -> 96 ---
    gemm_kernel<128, 96, 16, 0><<<(N + 127) / 128, dim3(12, 16)>>>(x, W1, N);
    k_zero_stats<<<1, 192>>>();
    gather96_kernel<<<296, 256>>>(b1, N);
    bn_relu_kernel<<<(N * 96 + 255) / 256, 256>>>(g1, be1, N);

    // --- layer 2: 96 -> 96 ---
    gemm_kernel<96, 96, 16, 1><<<(N + 127) / 128, dim3(12, 16)>>>(nullptr, W2, N);
    k_zero_stats<<<1, 192>>>();
    gather96_kernel<<<296, 256>>>(b2, N);
    bn_relu_kernel<<<(N * 96 + 255) / 256, 256>>>(g2, be2, N);

    // --- layer 3: 96 -> 32, then log_softmax ---
    gemm_kernel<96, 32, 32, 1><<<(N + 255) / 256, dim3(4, 32)>>>(nullptr, W3, N);
    gather32_softmax_kernel<<<(N + 7) / 8, 256>>>(b3, out, N);
}

// round 9
// speedup vs baseline: 1.5414x; 1.0304x over previous
#include <cuda_runtime.h>
#include <cstdint>
#include <cstddef>

#define NMAX 100000
#define EMAX 800000
#define HIDD 96
#define SCAN_BLK 1024

// ---------------- scratch (no allocations allowed) ----------------
__device__ __align__(16) float g_dinv[NMAX];
__device__ __align__(16) float g_hA[(size_t)NMAX * HIDD];   // GEMM out, prescaled by dinv[row]
__device__ __align__(16) float g_hB[(size_t)NMAX * HIDD];   // post-BN/ReLU features
__device__ __align__(16) float g_agg[(size_t)NMAX * HIDD];  // gather output (pre-BN)
__device__ __align__(16) float g_stats[2 * HIDD];           // [sum | sumsq]
__device__ int g_cnt[NMAX];
__device__ int g_off[NMAX + 1];
__device__ int g_cur[NMAX];
__device__ int g_srcs[EMAX];
__device__ int g_bsum[128];

// ---------------- CSR build ----------------
__global__ void k_zero_cnt(int N) {
    int i = blockIdx.x * blockDim.x + threadIdx.x;
    if (i < N) { g_cnt[i] = 0; g_cur[i] = 0; }
}
__global__ void k_hist(const int* __restrict__ dst, int E) {
    int e = blockIdx.x * blockDim.x + threadIdx.x;
    if (e < E) atomicAdd(&g_cnt[dst[e]], 1);
}
__global__ void k_scan_block(int N) {   // grid = nb, block = SCAN_BLK
    __shared__ int s[SCAN_BLK];
    int i = blockIdx.x * SCAN_BLK + threadIdx.x;
    int v = (i < N) ? g_cnt[i] : 0;
    s[threadIdx.x] = v;
    __syncthreads();
#pragma unroll
    for (int o = 1; o < SCAN_BLK; o <<= 1) {
        int t = (threadIdx.x >= o) ? s[threadIdx.x - o] : 0;
        __syncthreads();
        s[threadIdx.x] += t;
        __syncthreads();
    }
    if (i < N) g_off[i + 1] = s[threadIdx.x];
    if (threadIdx.x == SCAN_BLK - 1) g_bsum[blockIdx.x] = s[SCAN_BLK - 1];
}
__global__ void k_scan_bsum(int nb) {   // 1 block, 128 threads
    __shared__ int s[128];
    int v = (threadIdx.x < nb) ? g_bsum[threadIdx.x] : 0;
    s[threadIdx.x] = v;
    __syncthreads();
#pragma unroll
    for (int o = 1; o < 128; o <<= 1) {
        int t = (threadIdx.x >= o) ? s[threadIdx.x - o] : 0;
        __syncthreads();
        s[threadIdx.x] += t;
        __syncthreads();
    }
    if (threadIdx.x < nb) g_bsum[threadIdx.x] = s[threadIdx.x];
}
__global__ void k_scan_add(int N) {     // grid = nb, block = SCAN_BLK; also computes dinv
    int i = blockIdx.x * SCAN_BLK + threadIdx.x;
    if (blockIdx.x > 0 && i < N) g_off[i + 1] += g_bsum[blockIdx.x - 1];
    if (i == 0) g_off[0] = 0;
    if (i < N) g_dinv[i] = rsqrtf((float)(g_cnt[i] + 1));   // +1 self loop
}
__global__ void k_reorder(const int* __restrict__ src, const int* __restrict__ dst, int E) {
    int e = blockIdx.x * blockDim.x + threadIdx.x;
    if (e < E) {
        int d = dst[e];
        int pos = g_off[d] + atomicAdd(&g_cur[d], 1);
        g_srcs[pos] = src[e];
    }
}
__global__ void k_zero_stats() {
    int i = threadIdx.x;
    if (i < 2 * HIDD) g_stats[i] = 0.f;
}

// ---------------- GEMM: g_hA[N,OUT] = dinv[row] * (X[N,K] @ W[K,OUT]) ----------------
// 8 rows x 8 cols per thread. W staged in SMEM. USE_HB=1 -> X = g_hB.
__device__ __forceinline__ float f4c(const float4& v, int kk) {
    switch (kk) { case 0: return v.x; case 1: return v.y; case 2: return v.z; default: return v.w; }
}

template <int K, int OUT, int RY, int USE_HB>
__global__ __launch_bounds__((OUT / 8) * RY)
void gemm_kernel(const float* __restrict__ Xarg, const float* __restrict__ W, int N) {
    constexpr int CG = OUT / 8;   // thread col-groups
    constexpr int C4 = OUT / 4;
    __shared__ float4 Ws[K * C4];
    const int tid = threadIdx.y * CG + threadIdx.x;
    const float4* W4 = (const float4*)W;
    for (int i = tid; i < K * C4; i += CG * RY) Ws[i] = W4[i];
    __syncthreads();

    const float* X = USE_HB ? (const float*)g_hB : Xarg;
    const int c = threadIdx.x;
    const int r0 = (blockIdx.x * RY + threadIdx.y) * 8;
    if (r0 >= N) return;
    const bool full = (r0 + 7 < N);

    const float4* X4 = (const float4*)X;
    constexpr int ldx = K / 4;

    float4 acc[8][2];
#pragma unroll
    for (int r = 0; r < 8; r++) {
        acc[r][0] = make_float4(0.f, 0.f, 0.f, 0.f);
        acc[r][1] = make_float4(0.f, 0.f, 0.f, 0.f);
    }

    for (int k4 = 0; k4 < K / 4; k4++) {
        float4 xr[8];
#pragma unroll
        for (int r = 0; r < 8; r++) {
            int row = r0 + r;
            xr[r] = (full || row < N) ? X4[(size_t)row * ldx + k4]
                                      : make_float4(0.f, 0.f, 0.f, 0.f);
        }
#pragma unroll
        for (int kk = 0; kk < 4; kk++) {
            float4 w0 = Ws[(k4 * 4 + kk) * C4 + 2 * c];
            float4 w1 = Ws[(k4 * 4 + kk) * C4 + 2 * c + 1];
#pragma unroll
            for (int r = 0; r < 8; r++) {
                float xv = f4c(xr[r], kk);
                acc[r][0].x += xv * w0.x; acc[r][0].y += xv * w0.y;
                acc[r][0].z += xv * w0.z; acc[r][0].w += xv * w0.w;
                acc[r][1].x += xv * w1.x; acc[r][1].y += xv * w1.y;
                acc[r][1].z += xv * w1.z; acc[r][1].w += xv * w1.w;
            }
        }
    }

    float4* Y4 = (float4*)g_hA;
#pragma unroll
    for (int r = 0; r < 8; r++) {
        int row = r0 + r;
        if (full || row < N) {
            float dr = g_dinv[row];
            float4 a0 = acc[r][0], a1 = acc[r][1];
            a0.x *= dr; a0.y *= dr; a0.z *= dr; a0.w *= dr;
            a1.x *= dr; a1.y *= dr; a1.z *= dr; a1.w *= dr;
            Y4[(size_t)row * C4 + 2 * c]     = a0;
            Y4[(size_t)row * C4 + 2 * c + 1] = a1;
        }
    }
}

// ---------------- gather96: warp per node, CSR in-edges ----------------
// hA holds ĥ[s] = dinv[s]*h[s]; v[d] = dinv[d]*(Σ_in ĥ[s] + ĥ[d]) + b
// Fused BN-stat accumulation (smem reduce -> global atomics).
__global__ __launch_bounds__(256)
void gather96_kernel(const float* __restrict__ bias, int N) {
    __shared__ float sred[192];
    const int tid = threadIdx.x;
    for (int i = tid; i < 192; i += 256) sred[i] = 0.f;
    __syncthreads();

    const int lane = tid & 31;
    const int w = tid >> 5;
    const int c0 = lane, c1 = lane + 32, c2 = lane + 64;
    const float b0 = bias[c0], b1 = bias[c1], b2 = bias[c2];
    const int nwarps = gridDim.x * 8;

    float s0 = 0.f, s1 = 0.f, s2 = 0.f;       // BN sums
    float q0 = 0.f, q1 = 0.f, q2 = 0.f;       // BN sumsq

    for (int d = blockIdx.x * 8 + w; d < N; d += nwarps) {
        const int beg = g_off[d];
        const int end = g_off[d + 1];
        float a0 = 0.f, a1 = 0.f, a2 = 0.f;
        int j = beg;
        for (; j + 3 < end; j += 4) {
            int sa = g_srcs[j], sb = g_srcs[j + 1], sc = g_srcs[j + 2], se = g_srcs[j + 3];
            const float* ha = g_hA + (size_t)sa * 96;
            const float* hb = g_hA + (size_t)sb * 96;
            const float* hc = g_hA + (size_t)sc * 96;
            const float* he = g_hA + (size_t)se * 96;
            float x0a = ha[c0], x1a = ha[c1], x2a = ha[c2];
            float x0b = hb[c0], x1b = hb[c1], x2b = hb[c2];
            float x0c = hc[c0], x1c = hc[c1], x2c = hc[c2];
            float x0e = he[c0], x1e = he[c1], x2e = he[c2];
            a0 += (x0a + x0b) + (x0c + x0e);
            a1 += (x1a + x1b) + (x1c + x1e);
            a2 += (x2a + x2b) + (x2c + x2e);
        }
        for (; j < end; j++) {
            int sa = g_srcs[j];
            const float* ha = g_hA + (size_t)sa * 96;
            a0 += ha[c0]; a1 += ha[c1]; a2 += ha[c2];
        }
        const float dd = g_dinv[d];
        const float* hd = g_hA + (size_t)d * 96;
        a0 += hd[c0]; a1 += hd[c1]; a2 += hd[c2];
        float v0 = dd * a0 + b0;
        float v1 = dd * a1 + b1;
        float v2 = dd * a2 + b2;
        float* od = g_agg + (size_t)d * 96;
        od[c0] = v0; od[c1] = v1; od[c2] = v2;
        s0 += v0; s1 += v1; s2 += v2;
        q0 += v0 * v0; q1 += v1 * v1; q2 += v2 * v2;
    }

    atomicAdd(&sred[c0], s0); atomicAdd(&sred[c1], s1); atomicAdd(&sred[c2], s2);
    atomicAdd(&sred[96 + c0], q0); atomicAdd(&sred[96 + c1], q1); atomicAdd(&sred[96 + c2], q2);
    __syncthreads();
    for (int i = tid; i < 192; i += 256) atomicAdd(&g_stats[i], sred[i]);
}

// ---------------- BN apply + ReLU: g_hB = relu(bn(g_agg)) ----------------
__global__ void bn_relu_kernel(const float* __restrict__ gamma,
                               const float* __restrict__ beta, int N) {
    int idx = blockIdx.x * blockDim.x + threadIdx.x;
    int total = N * HIDD;
    if (idx >= total) return;
    int f = idx - (idx / HIDD) * HIDD;
    float invN = 1.0f / (float)N;
    float mu = g_stats[f] * invN;
    float var = g_stats[HIDD + f] * invN - mu * mu;
    float y = gamma[f] * (g_agg[idx] - mu) * rsqrtf(var + 1e-5f) + beta[f];
    g_hB[idx] = fmaxf(y, 0.f);
}

// ---------------- layer-3: gather(32) + log_softmax, warp per node ----------------
__global__ __launch_bounds__(256)
void gather32_softmax_kernel(const float* __restrict__ b3, float* __restrict__ out, int N) {
    int d = blockIdx.x * 8 + (threadIdx.x >> 5);
    int lane = threadIdx.x & 31;
    if (d >= N) return;
    const int beg = g_off[d];
    const int end = g_off[d + 1];
    float a = 0.f;
    int j = beg;
    for (; j + 3 < end; j += 4) {
        int sa = g_srcs[j], sb = g_srcs[j + 1], sc = g_srcs[j + 2], se = g_srcs[j + 3];
        float xa = g_hA[(size_t)sa * 32 + lane];
        float xb = g_hA[(size_t)sb * 32 + lane];
        float xc = g_hA[(size_t)sc * 32 + lane];
        float xe = g_hA[(size_t)se * 32 + lane];
        a += (xa + xb) + (xc + xe);
    }
    for (; j < end; j++) {
        int sa = g_srcs[j];
        a += g_hA[(size_t)sa * 32 + lane];
    }
    float dd = g_dinv[d];
    a += g_hA[(size_t)d * 32 + lane];
    float v = dd * a + b3[lane];
    float m = v;
#pragma unroll
    for (int o = 16; o > 0; o >>= 1) m = fmaxf(m, __shfl_xor_sync(0xFFFFFFFFu, m, o));
    float s = expf(v - m);
#pragma unroll
    for (int o = 16; o > 0; o >>= 1) s += __shfl_xor_sync(0xFFFFFFFFu, s, o);
    out[(size_t)d * 32 + lane] = v - m - logf(s);
}

// ---------------- host ----------------
extern "C" void kernel_launch(void* const* d_in, const int* in_sizes, int n_in,
                              void* d_out, int out_size) {
    const float* x  = (const float*)d_in[0];
    const int* ei   = (const int*)d_in[1];   // int32 in practice (JAX x64 disabled)
    const float* W1 = (const float*)d_in[2];
    const float* b1 = (const float*)d_in[3];
    const float* W2 = (const float*)d_in[4];
    const float* b2 = (const float*)d_in[5];
    const float* W3 = (const float*)d_in[6];
    const float* b3 = (const float*)d_in[7];
    const float* g1 = (const float*)d_in[8];
    const float* be1 = (const float*)d_in[9];
    const float* g2 = (const float*)d_in[10];
    const float* be2 = (const float*)d_in[11];
    float* out = (float*)d_out;

    int N = in_sizes[0] / 128;
    int E = in_sizes[1] / 2;
    const int* src = ei;
    const int* dst = ei + E;

    // --- CSR build (once per call, reused by all 3 layers) ---
    int nb = (N + SCAN_BLK - 1) / SCAN_BLK;
    k_zero_cnt<<<(N + 255) / 256, 256>>>(N);
    k_hist<<<(E + 255) / 256, 256>>>(dst, E);
    k_scan_block<<<nb, SCAN_BLK>>>(N);
    k_scan_bsum<<<1, 128>>>(nb);
    k_scan_add<<<nb, SCAN_BLK>>>(N);      // also computes dinv
    k_reorder<<<(E + 255) / 256, 256>>>(src, dst, E);

    // --- layer 1: 128 -> 96 ---
    gemm_kernel<128, 96, 16, 0><<<(N + 127) / 128, dim3(12, 16)>>>(x, W1, N);
    k_zero_stats<<<1, 192>>>();
    gather96_kernel<<<296, 256>>>(b1, N);
    bn_relu_kernel<<<(N * 96 + 255) / 256, 256>>>(g1, be1, N);

    // --- layer 2: 96 -> 96 ---
    gemm_kernel<96, 96, 16, 1><<<(N + 127) / 128, dim3(12, 16)>>>(nullptr, W2, N);
    k_zero_stats<<<1, 192>>>();
    gather96_kernel<<<296, 256>>>(b2, N);
    bn_relu_kernel<<<(N * 96 + 255) / 256, 256>>>(g2, be2, N);

    // --- layer 3: 96 -> 32, then log_softmax ---
    gemm_kernel<96, 32, 32, 1><<<(N + 255) / 256, dim3(4, 32)>>>(nullptr, W3, N);
    gather32_softmax_kernel<<<(N + 7) / 8, 256>>>(b3, out, N);
}

// round 10
// speedup vs baseline: 1.9671x; 1.2762x over previous
#include <cuda_runtime.h>
#include <cstdint>
#include <cstddef>

#define NMAX 100000
#define EMAX 800000
#define HIDD 96
#define SCAN_BLK 1024

// ---------------- scratch (no allocations allowed) ----------------
__device__ __align__(16) float g_dinv[NMAX];
__device__ __align__(16) float g_hA[(size_t)NMAX * HIDD];   // GEMM out, prescaled by dinv[row]
__device__ __align__(16) float g_agg[(size_t)NMAX * HIDD];  // gather output (pre-BN)
__device__ __align__(16) float g_stats[2 * 192];            // per-layer [sum(96) | sumsq(96)]
__device__ int g_cnt[NMAX];
__device__ int g_off[NMAX + 1];
__device__ int g_cur[NMAX];
__device__ int g_srcs[EMAX];
__device__ int g_pub[128];                                  // decoupled-scan publish slots

// ---------------- zero everything that needs zeroing (one kernel) ----------------
__global__ void k_zero(int N, int nb) {
    int i = blockIdx.x * blockDim.x + threadIdx.x;
    if (i < N) { g_cnt[i] = 0; g_cur[i] = 0; }
    if (i < nb) g_pub[i] = 0;
    if (i < 2 * 192) g_stats[i] = 0.f;
}
__global__ void k_hist(const int* __restrict__ dst, int E) {
    int e = blockIdx.x * blockDim.x + threadIdx.x;
    if (e < E) atomicAdd(&g_cnt[dst[e]], 1);
}

// ---------------- fused exclusive scan + dinv (decoupled raking) ----------------
__global__ __launch_bounds__(SCAN_BLK)
void k_scan(int N) {
    __shared__ int s[SCAN_BLK];
    __shared__ int wsum[32];
    __shared__ int base_sh;
    const int tid = threadIdx.x;
    const int b = blockIdx.x;
    const int i = b * SCAN_BLK + tid;
    const int myc = (i < N) ? g_cnt[i] : 0;

    // inclusive block scan
    s[tid] = myc;
    __syncthreads();
#pragma unroll
    for (int o = 1; o < SCAN_BLK; o <<= 1) {
        int t = (tid >= o) ? s[tid - o] : 0;
        __syncthreads();
        s[tid] += t;
        __syncthreads();
    }

    // publish this block's total (+1 so 0 means "not ready")
    if (tid == SCAN_BLK - 1) atomicExch(&g_pub[b], s[SCAN_BLK - 1] + 1);

    // sum all predecessor totals (raking lookback; blocks publish independently)
    int p = 0;
    if (tid < b) {
        int v;
        do { v = atomicAdd(&g_pub[tid], 0); } while (v == 0);
        p = v - 1;
    }
#pragma unroll
    for (int o = 16; o > 0; o >>= 1) p += __shfl_xor_sync(0xFFFFFFFFu, p, o);
    if ((tid & 31) == 0) wsum[tid >> 5] = p;
    __syncthreads();
    if (tid == 0) {
        int a = 0;
#pragma unroll
        for (int wgi = 0; wgi < 32; wgi++) a += wsum[wgi];
        base_sh = a;
    }
    __syncthreads();
    const int base = base_sh;

    if (i < N) {
        g_off[i + 1] = base + s[tid];
        g_dinv[i] = rsqrtf((float)(myc + 1));   // +1 self loop
    }
    if (b == 0 && tid == 0) g_off[0] = 0;
}

__global__ void k_reorder(const int* __restrict__ src, const int* __restrict__ dst, int E) {
    int e = blockIdx.x * blockDim.x + threadIdx.x;
    if (e < E) {
        int d = dst[e];
        int pos = g_off[d] + atomicAdd(&g_cur[d], 1);
        g_srcs[pos] = src[e];
    }
}

// ---------------- GEMM: g_hA[N,OUT] = dinv[row] * (act(X)[N,K] @ W[K,OUT]) ----------------
// MODE 0: X = external pointer, no activation (layer 1).
// MODE 1/2: X = g_agg with fused BN(stats layer MODE-1)+ReLU per element.
__device__ __forceinline__ float f4c(const float4& v, int kk) {
    switch (kk) { case 0: return v.x; case 1: return v.y; case 2: return v.z; default: return v.w; }
}

template <int K, int OUT, int RY, int MODE>
__global__ __launch_bounds__((OUT / 8) * RY)
void gemm_kernel(const float* __restrict__ Xarg, const float* __restrict__ W,
                 const float* __restrict__ gamma, const float* __restrict__ beta, int N) {
    constexpr int CG = OUT / 8;   // thread col-groups
    constexpr int C4 = OUT / 4;
    __shared__ float4 Ws[K * C4];
    __shared__ float sa[MODE ? K : 1];
    __shared__ float sc[MODE ? K : 1];
    const int tid = threadIdx.y * CG + threadIdx.x;
    const float4* W4 = (const float4*)W;
    for (int i = tid; i < K * C4; i += CG * RY) Ws[i] = W4[i];
    if (MODE) {
        const float* st = g_stats + (MODE - 1) * 192;
        for (int f = tid; f < K; f += CG * RY) {
            float invN = 1.0f / (float)N;
            float mu = st[f] * invN;
            float var = st[96 + f] * invN - mu * mu;
            float a = gamma[f] * rsqrtf(var + 1e-5f);
            sa[f] = a;
            sc[f] = beta[f] - mu * a;
        }
    }
    __syncthreads();

    const float* X = MODE ? (const float*)g_agg : Xarg;
    const int c = threadIdx.x;
    const int r0 = (blockIdx.x * RY + threadIdx.y) * 8;
    if (r0 >= N) return;
    const bool full = (r0 + 7 < N);

    const float4* X4 = (const float4*)X;
    constexpr int ldx = K / 4;

    float4 acc[8][2];
#pragma unroll
    for (int r = 0; r < 8; r++) {
        acc[r][0] = make_float4(0.f, 0.f, 0.f, 0.f);
        acc[r][1] = make_float4(0.f, 0.f, 0.f, 0.f);
    }

    for (int k4 = 0; k4 < K / 4; k4++) {
        float4 xr[8];
        float4 ba, bc;
        if (MODE) { ba = ((const float4*)sa)[k4]; bc = ((const float4*)sc)[k4]; }
#pragma unroll
        for (int r = 0; r < 8; r++) {
            int row = r0 + r;
            float4 v = (full || row < N) ? X4[(size_t)row * ldx + k4]
                                         : make_float4(0.f, 0.f, 0.f, 0.f);
            if (MODE) {
                v.x = fmaxf(ba.x * v.x + bc.x, 0.f);
                v.y = fmaxf(ba.y * v.y + bc.y, 0.f);
                v.z = fmaxf(ba.z * v.z + bc.z, 0.f);
                v.w = fmaxf(ba.w * v.w + bc.w, 0.f);
            }
            xr[r] = v;
        }
#pragma unroll
        for (int kk = 0; kk < 4; kk++) {
            float4 w0 = Ws[(k4 * 4 + kk) * C4 + 2 * c];
            float4 w1 = Ws[(k4 * 4 + kk) * C4 + 2 * c + 1];
#pragma unroll
            for (int r = 0; r < 8; r++) {
                float xv = f4c(xr[r], kk);
                acc[r][0].x += xv * w0.x; acc[r][0].y += xv * w0.y;
                acc[r][0].z += xv * w0.z; acc[r][0].w += xv * w0.w;
                acc[r][1].x += xv * w1.x; acc[r][1].y += xv * w1.y;
                acc[r][1].z += xv * w1.z; acc[r][1].w += xv * w1.w;
            }
        }
    }

    float4* Y4 = (float4*)g_hA;
#pragma unroll
    for (int r = 0; r < 8; r++) {
        int row = r0 + r;
        if (full || row < N) {
            float dr = g_dinv[row];
            float4 a0 = acc[r][0], a1 = acc[r][1];
            a0.x *= dr; a0.y *= dr; a0.z *= dr; a0.w *= dr;
            a1.x *= dr; a1.y *= dr; a1.z *= dr; a1.w *= dr;
            Y4[(size_t)row * C4 + 2 * c]     = a0;
            Y4[(size_t)row * C4 + 2 * c + 1] = a1;
        }
    }
}

// ---------------- gather96: warp per node, CSR in-edges ----------------
// hA holds ĥ[s] = dinv[s]*h[s]; v[d] = dinv[d]*(Σ_in ĥ[s] + ĥ[d]) + b
// Fused BN-stat accumulation into g_stats[layer].
__global__ __launch_bounds__(256)
void gather96_kernel(const float* __restrict__ bias, int layer, int N) {
    __shared__ float sred[192];
    const int tid = threadIdx.x;
    for (int i = tid; i < 192; i += 256) sred[i] = 0.f;
    __syncthreads();

    const int lane = tid & 31;
    const int w = tid >> 5;
    const int c0 = lane, c1 = lane + 32, c2 = lane + 64;
    const float b0 = bias[c0], b1 = bias[c1], b2 = bias[c2];
    const int nwarps = gridDim.x * 8;

    float s0 = 0.f, s1 = 0.f, s2 = 0.f;
    float q0 = 0.f, q1 = 0.f, q2 = 0.f;

    for (int d = blockIdx.x * 8 + w; d < N; d += nwarps) {
        const int beg = g_off[d];
        const int end = g_off[d + 1];
        float a0 = 0.f, a1 = 0.f, a2 = 0.f;
        int j = beg;
        for (; j + 3 < end; j += 4) {
            int sa = g_srcs[j], sb = g_srcs[j + 1], sc = g_srcs[j + 2], se = g_srcs[j + 3];
            const float* ha = g_hA + (size_t)sa * 96;
            const float* hb = g_hA + (size_t)sb * 96;
            const float* hc = g_hA + (size_t)sc * 96;
            const float* he = g_hA + (size_t)se * 96;
            float x0a = ha[c0], x1a = ha[c1], x2a = ha[c2];
            float x0b = hb[c0], x1b = hb[c1], x2b = hb[c2];
            float x0c = hc[c0], x1c = hc[c1], x2c = hc[c2];
            float x0e = he[c0], x1e = he[c1], x2e = he[c2];
            a0 += (x0a + x0b) + (x0c + x0e);
            a1 += (x1a + x1b) + (x1c + x1e);
            a2 += (x2a + x2b) + (x2c + x2e);
        }
        for (; j < end; j++) {
            int sa = g_srcs[j];
            const float* ha = g_hA + (size_t)sa * 96;
            a0 += ha[c0]; a1 += ha[c1]; a2 += ha[c2];
        }
        const float dd = g_dinv[d];
        const float* hd = g_hA + (size_t)d * 96;
        a0 += hd[c0]; a1 += hd[c1]; a2 += hd[c2];
        float v0 = dd * a0 + b0;
        float v1 = dd * a1 + b1;
        float v2 = dd * a2 + b2;
        float* od = g_agg + (size_t)d * 96;
        od[c0] = v0; od[c1] = v1; od[c2] = v2;
        s0 += v0; s1 += v1; s2 += v2;
        q0 += v0 * v0; q1 += v1 * v1; q2 += v2 * v2;
    }

    atomicAdd(&sred[c0], s0); atomicAdd(&sred[c1], s1); atomicAdd(&sred[c2], s2);
    atomicAdd(&sred[96 + c0], q0); atomicAdd(&sred[96 + c1], q1); atomicAdd(&sred[96 + c2], q2);
    __syncthreads();
    float* st = g_stats + layer * 192;
    for (int i = tid; i < 192; i += 256) atomicAdd(&st[i], sred[i]);
}

// ---------------- layer-3: gather(32) + log_softmax, warp per node ----------------
__global__ __launch_bounds__(256)
void gather32_softmax_kernel(const float* __restrict__ b3, float* __restrict__ out, int N) {
    int d = blockIdx.x * 8 + (threadIdx.x >> 5);
    int lane = threadIdx.x & 31;
    if (d >= N) return;
    const int beg = g_off[d];
    const int end = g_off[d + 1];
    float a = 0.f;
    int j = beg;
    for (; j + 3 < end; j += 4) {
        int sa = g_srcs[j], sb = g_srcs[j + 1], sc = g_srcs[j + 2], se = g_srcs[j + 3];
        float xa = g_hA[(size_t)sa * 32 + lane];
        float xb = g_hA[(size_t)sb * 32 + lane];
        float xc = g_hA[(size_t)sc * 32 + lane];
        float xe = g_hA[(size_t)se * 32 + lane];
        a += (xa + xb) + (xc + xe);
    }
    for (; j < end; j++) {
        int sa = g_srcs[j];
        a += g_hA[(size_t)sa * 32 + lane];
    }
    float dd = g_dinv[d];
    a += g_hA[(size_t)d * 32 + lane];
    float v = dd * a + b3[lane];
    float m = v;
#pragma unroll
    for (int o = 16; o > 0; o >>= 1) m = fmaxf(m, __shfl_xor_sync(0xFFFFFFFFu, m, o));
    float s = expf(v - m);
#pragma unroll
    for (int o = 16; o > 0; o >>= 1) s += __shfl_xor_sync(0xFFFFFFFFu, s, o);
    out[(size_t)d * 32 + lane] = v - m - logf(s);
}

// ---------------- host ----------------
extern "C" void kernel_launch(void* const* d_in, const int* in_sizes, int n_in,
                              void* d_out, int out_size) {
    const float* x  = (const float*)d_in[0];
    const int* ei   = (const int*)d_in[1];   // int32 in practice (JAX x64 disabled)
    const float* W1 = (const float*)d_in[2];
    const float* b1 = (const float*)d_in[3];
    const float* W2 = (const float*)d_in[4];
    const float* b2 = (const float*)d_in[5];
    const float* W3 = (const float*)d_in[6];
    const float* b3 = (const float*)d_in[7];
    const float* g1 = (const float*)d_in[8];
    const float* be1 = (const float*)d_in[9];
    const float* g2 = (const float*)d_in[10];
    const float* be2 = (const float*)d_in[11];
    float* out = (float*)d_out;

    int N = in_sizes[0] / 128;
    int E = in_sizes[1] / 2;
    const int* src = ei;
    const int* dst = ei + E;
    int nb = (N + SCAN_BLK - 1) / SCAN_BLK;

    // --- CSR build: 4 kernels ---
    k_zero<<<(N + 1023) / 1024, 1024>>>(N, nb);
    k_hist<<<(E + 255) / 256, 256>>>(dst, E);
    k_scan<<<nb, SCAN_BLK>>>(N);                 // fused scan + dinv (decoupled raking)
    // gemm1 only needs dinv -> launch before reorder so it overlaps profiling slot
    gemm_kernel<128, 96, 16, 0><<<(N + 127) / 128, dim3(12, 16)>>>(x, W1, nullptr, nullptr, N);
    k_reorder<<<(E + 255) / 256, 256>>>(src, dst, E);

    // --- layer 1 ---
    gather96_kernel<<<592, 256>>>(b1, 0, N);

    // --- layer 2 (BN+ReLU of layer 1 fused into X-load) ---
    gemm_kernel<96, 96, 16, 1><<<(N + 127) / 128, dim3(12, 16)>>>(nullptr, W2, g1, be1, N);
    gather96_kernel<<<592, 256>>>(b2, 1, N);

    // --- layer 3 (BN+ReLU of layer 2 fused), then gather+log_softmax ---
    gemm_kernel<96, 32, 32, 2><<<(N + 255) / 256, dim3(4, 32)>>>(nullptr, W3, g2, be2, N);
    gather32_softmax_kernel<<<(N + 7) / 8, 256>>>(b3, out, N);
}